// round 12
// baseline (speedup 1.0000x reference)
#include <cuda_runtime.h>
#include <math.h>

#define NN 16384
#define GIN 1568
#define EMAX 540672   // 524288 + NN

// ---------------- scratch (static __device__, no allocation) ----------------
__device__ float d_h0[(size_t)NN * GIN];
__device__ float d_xl1[(size_t)NN * 128];
__device__ float d_xr1[(size_t)NN * 128];
__device__ float d_h1[(size_t)NN * 128];
__device__ float d_xl2[(size_t)NN * 64];
__device__ float d_xr2[(size_t)NN * 64];
__device__ float d_h2[(size_t)NN * 64];
__device__ int d_deg[NN];
__device__ int d_rowstart[NN + 1];
__device__ int d_cursor[NN];
__device__ int d_csrc[EMAX];

// ---------------- helpers ----------------
__device__ __forceinline__ unsigned f2tf32(float x) {
    unsigned u;
    asm("cvt.rna.tf32.f32 %0, %1;" : "=r"(u) : "f"(x));
    return u;
}
__device__ __forceinline__ void mma_tf32(float* d, const unsigned* a, const unsigned* b) {
    asm volatile(
        "mma.sync.aligned.m16n8k8.row.col.f32.tf32.tf32.f32 "
        "{%0,%1,%2,%3}, {%4,%5,%6,%7}, {%8,%9}, {%0,%1,%2,%3};\n"
        : "+f"(d[0]), "+f"(d[1]), "+f"(d[2]), "+f"(d[3])
        : "r"(a[0]), "r"(a[1]), "r"(a[2]), "r"(a[3]), "r"(b[0]), "r"(b[1]));
}
__device__ __forceinline__ unsigned smaddr(const void* p) {
    unsigned a;
    asm("{ .reg .u64 t; cvta.to.shared.u64 t, %1; cvt.u32.u64 %0, t; }" : "=r"(a) : "l"(p));
    return a;
}
__device__ __forceinline__ void cp16(unsigned d, const void* s) {
    asm volatile("cp.async.cg.shared.global [%0], [%1], 16;" :: "r"(d), "l"(s));
}

// ---------------- fused conv1+pool+conv2+pool (tf32 implicit GEMM) ----------------
// Smem plan (words; total 9428 = 36.8KB -> 6 blocks/SM):
//   [0..4100)      sInP: 16ci x 256 padded conv1 output, tf32 bits
//   [4100..9284)   overlay: {sImg 784 | sW1 144 | sB1 16} during conv1,
//                  then Bs[144][36] (conv2 weights, tf32) for the mainloop
//   [9284..9428)   offT[144]
//   epilogue: sC[224][33] overlays [0..7392)
#define C2_BP 36
__global__ void k_convf(const float* __restrict__ x,
                        const float* __restrict__ w1,
                        const float* __restrict__ b1,
                        const float* __restrict__ w2,
                        const float* __restrict__ b2) {
    __shared__ float S[9428];
    unsigned* sInP = (unsigned*)S;              // [0..4100)
    float*    sImg = S + 4100;                  // conv1 phase
    float*    sW1  = S + 4884;
    float*    sB1  = S + 5028;                  // 5028..5044
    unsigned* Bs   = (unsigned*)(S + 4100);     // mainloop phase (overlays sImg/sW1)
    int*      offT = (int*)(S + 9284);
    float*    sC   = S;                         // epilogue overlay

    int n = blockIdx.x, tid = threadIdx.x;

    // ---- stage image + conv1 weights + offsets; zero padded tile ----
    for (int i = tid; i < 4100; i += 256) sInP[i] = 0u;
    const float* xp = x + (size_t)n * 784;
    for (int i = tid; i < 784; i += 256) sImg[i] = xp[i];
    if (tid < 144) sW1[tid] = w1[tid];
    if (tid < 16) sB1[tid] = b1[tid];
    if (tid < 144) {
        int ci = tid / 9, rem = tid - ci * 9;
        offT[tid] = ci * 256 + (rem / 3) * 16 + (rem % 3);
    }
    __syncthreads();

    // ---- conv1 + relu + maxpool -> sInP (padded, tf32 bits) ----
    for (int item = tid; item < 784; item += 256) {
        int ct = item / 196;
        int pos = item % 196;
        int py = pos / 14, px = pos % 14;
        int y0 = 2 * py - 1, x0 = 2 * px - 1;
        float patch[4][4];
        #pragma unroll
        for (int r = 0; r < 4; r++) {
            int iy = y0 + r;
            bool okY = (unsigned)iy < 28u;
            #pragma unroll
            for (int cc = 0; cc < 4; cc++) {
                int ix = x0 + cc;
                patch[r][cc] = (okY && (unsigned)ix < 28u) ? sImg[iy * 28 + ix] : 0.f;
            }
        }
        #pragma unroll
        for (int c8 = 0; c8 < 4; c8++) {
            int c = ct * 4 + c8;
            float bb = sB1[c];
            float a0 = bb, a1 = bb, a2 = bb, a3 = bb;
            const float* wp = &sW1[c * 9];
            #pragma unroll
            for (int ky = 0; ky < 3; ky++) {
                #pragma unroll
                for (int kx = 0; kx < 3; kx++) {
                    float wv = wp[ky * 3 + kx];
                    a0 += patch[ky][kx]         * wv;
                    a1 += patch[ky][kx + 1]     * wv;
                    a2 += patch[ky + 1][kx]     * wv;
                    a3 += patch[ky + 1][kx + 1] * wv;
                }
            }
            float best = fmaxf(fmaxf(a0, a1), fmaxf(a2, a3));
            sInP[c * 256 + (py + 1) * 16 + px + 1] = f2tf32(fmaxf(best, 0.f));
        }
    }
    __syncthreads();

    // ---- stage conv2 weights (overlays conv1 staging region) ----
    for (int i = tid; i < 4608; i += 256) {     // w2 (32,16,3,3): Bs[k][oc]
        int oc = i / 144, k = i - oc * 144;
        Bs[k * C2_BP + oc] = f2tf32(__ldg(&w2[i]));
    }
    __syncthreads();

    // ---- conv2 mainloop: zero-staging implicit GEMM, no cvt, no syncs ----
    int warp = tid >> 5, lane = tid & 31;
    int g = lane >> 2, t = lane & 3;

    float acc[2][4][4] = {};

    #pragma unroll
    for (int chunk = 0; chunk < 9; chunk++) {
        int c16 = chunk * 16;
        int o0 = offT[c16 + t];
        int o1 = offT[c16 + t + 4];
        int o2 = offT[c16 + t + 8];
        int o3 = offT[c16 + t + 12];
        #pragma unroll
        for (int kb = 0; kb < 2; kb++) {
            int oA = kb ? o2 : o0, oB = kb ? o3 : o1;
            int krow = c16 + kb * 8;
            unsigned bfr[4][2];
            #pragma unroll
            for (int ni = 0; ni < 4; ni++) {
                bfr[ni][0] = Bs[(krow + t) * C2_BP + ni * 8 + g];
                bfr[ni][1] = Bs[(krow + t + 4) * C2_BP + ni * 8 + g];
            }
            #pragma unroll
            for (int mi = 0; mi < 2; mi++) {
                int mt = warp + mi * 8;
                if (mt < 14) {
                    int m = mt * 16;
                    unsigned a[4];
                    a[0] = sInP[oA + m + g];
                    a[1] = sInP[oA + m + g + 8];
                    a[2] = sInP[oB + m + g];
                    a[3] = sInP[oB + m + g + 8];
                    #pragma unroll
                    for (int ni = 0; ni < 4; ni++)
                        mma_tf32(acc[mi][ni], a, bfr[ni]);
                }
            }
        }
    }
    __syncthreads();   // all smem dead; reuse as sC

    #pragma unroll
    for (int mi = 0; mi < 2; mi++) {
        int mt = warp + mi * 8;
        if (mt < 14) {
            int row0 = mt * 16 + g;
            #pragma unroll
            for (int ni = 0; ni < 4; ni++) {
                int col = ni * 8 + t * 2;
                sC[row0 * 33 + col]           = acc[mi][ni][0];
                sC[row0 * 33 + col + 1]       = acc[mi][ni][1];
                sC[(row0 + 8) * 33 + col]     = acc[mi][ni][2];
                sC[(row0 + 8) * 33 + col + 1] = acc[mi][ni][3];
            }
        }
    }
    __syncthreads();

    for (int o = tid; o < 1568; o += 256) {
        int oc = o / 49, p = o - oc * 49;
        int py = p / 7, px = p - py * 7;
        int pos00 = py * 32 + px * 2;
        float v = fmaxf(fmaxf(sC[pos00 * 33 + oc],        sC[(pos00 + 1) * 33 + oc]),
                        fmaxf(sC[(pos00 + 16) * 33 + oc], sC[(pos00 + 17) * 33 + oc]));
        v += __ldg(&b2[oc]);
        d_h0[(size_t)n * 1568 + o] = fmaxf(v, 0.f);
    }
}

// ---------------- dual tf32 GEMM: stages A once, computes l AND r outputs ----------------
template <int SEL>
__global__ void k_gemmd(const float* __restrict__ Bl, const float* __restrict__ biasl,
                        const float* __restrict__ Br, const float* __restrict__ biasr,
                        int K, int Nc) {
    const float* A = (SEL == 0) ? d_h0 : d_h1;
    float* Cl = (SEL == 0) ? d_xl1 : d_xl2;
    float* Cr = (SEL == 0) ? d_xr1 : d_xr2;

    __shared__ float As[2][128][20];
    __shared__ float Bsl[2][16][72];
    __shared__ float Bsr[2][16][72];

    int bm = blockIdx.y * 128, bn = blockIdx.x * 64;
    int tid = threadIdx.x;
    int warp = tid >> 5, lane = tid & 31;
    int g = lane >> 2, t = lane & 3;
    int mW = (warp >> 1) * 32, nW = (warp & 1) * 32;

    int arow = tid >> 1, akq = (tid & 1) * 8;
    int brow = tid >> 4, bq = (tid & 15) * 4;

    const float* aSrc  = A + (size_t)(bm + arow) * K + akq;
    const float* blSrc = Bl + (size_t)brow * Nc + bn + bq;
    const float* brSrc = Br + (size_t)brow * Nc + bn + bq;

    float accL[2][4][4] = {}, accR[2][4][4] = {};
    int niter = K >> 4;

    cp16(smaddr(&As[0][arow][akq]),     aSrc);
    cp16(smaddr(&As[0][arow][akq + 4]), aSrc + 4);
    cp16(smaddr(&Bsl[0][brow][bq]),     blSrc);
    cp16(smaddr(&Bsr[0][brow][bq]),     brSrc);
    asm volatile("cp.async.commit_group;");

    for (int it = 0; it < niter; it++) {
        int buf = it & 1;
        if (it + 1 < niter) {
            int k0 = (it + 1) << 4;
            cp16(smaddr(&As[buf ^ 1][arow][akq]),     aSrc + k0);
            cp16(smaddr(&As[buf ^ 1][arow][akq + 4]), aSrc + k0 + 4);
            cp16(smaddr(&Bsl[buf ^ 1][brow][bq]),     blSrc + (size_t)k0 * Nc);
            cp16(smaddr(&Bsr[buf ^ 1][brow][bq]),     brSrc + (size_t)k0 * Nc);
            asm volatile("cp.async.commit_group;");
            asm volatile("cp.async.wait_group 1;");
        } else {
            asm volatile("cp.async.wait_group 0;");
        }
        __syncthreads();

        #pragma unroll
        for (int kb = 0; kb < 2; kb++) {
            int kk = kb * 8;
            unsigned a[2][4], bL[4][2], bR[4][2];
            #pragma unroll
            for (int mi = 0; mi < 2; mi++) {
                int mrow = mW + mi * 16;
                float x0 = As[buf][mrow + g][kk + t];
                float x1 = As[buf][mrow + g + 8][kk + t];
                float x2 = As[buf][mrow + g][kk + t + 4];
                float x3 = As[buf][mrow + g + 8][kk + t + 4];
                if (SEL == 1) {
                    x0 = fmaxf(x0, 0.f); x1 = fmaxf(x1, 0.f);
                    x2 = fmaxf(x2, 0.f); x3 = fmaxf(x3, 0.f);
                }
                a[mi][0] = f2tf32(x0); a[mi][1] = f2tf32(x1);
                a[mi][2] = f2tf32(x2); a[mi][3] = f2tf32(x3);
            }
            #pragma unroll
            for (int ni = 0; ni < 4; ni++) {
                bL[ni][0] = f2tf32(Bsl[buf][kk + t][nW + ni * 8 + g]);
                bL[ni][1] = f2tf32(Bsl[buf][kk + t + 4][nW + ni * 8 + g]);
                bR[ni][0] = f2tf32(Bsr[buf][kk + t][nW + ni * 8 + g]);
                bR[ni][1] = f2tf32(Bsr[buf][kk + t + 4][nW + ni * 8 + g]);
            }
            #pragma unroll
            for (int mi = 0; mi < 2; mi++)
                #pragma unroll
                for (int ni = 0; ni < 4; ni++) {
                    mma_tf32(accL[mi][ni], a[mi], bL[ni]);
                    mma_tf32(accR[mi][ni], a[mi], bR[ni]);
                }
        }
        __syncthreads();
    }

    #pragma unroll
    for (int mi = 0; mi < 2; mi++) {
        int row0 = bm + mW + mi * 16 + g;
        #pragma unroll
        for (int ni = 0; ni < 4; ni++) {
            int col = bn + nW + ni * 8 + t * 2;
            float bl0 = biasl[col], bl1 = biasl[col + 1];
            float br0 = biasr[col], br1 = biasr[col + 1];
            Cl[(size_t)row0 * Nc + col]           = accL[mi][ni][0] + bl0;
            Cl[(size_t)row0 * Nc + col + 1]       = accL[mi][ni][1] + bl1;
            Cl[(size_t)(row0 + 8) * Nc + col]     = accL[mi][ni][2] + bl0;
            Cl[(size_t)(row0 + 8) * Nc + col + 1] = accL[mi][ni][3] + bl1;
            Cr[(size_t)row0 * Nc + col]           = accR[mi][ni][0] + br0;
            Cr[(size_t)row0 * Nc + col + 1]       = accR[mi][ni][1] + br1;
            Cr[(size_t)(row0 + 8) * Nc + col]     = accR[mi][ni][2] + br0;
            Cr[(size_t)(row0 + 8) * Nc + col + 1] = accR[mi][ni][3] + br1;
        }
    }
}

// ---------------- CSR build ----------------
__global__ void k_deg_init() {
    int i = blockIdx.x * blockDim.x + threadIdx.x;
    if (i < NN) d_deg[i] = 1;
}
__global__ void k_hist(const int* __restrict__ ei, int Eraw) {
    int i = blockIdx.x * blockDim.x + threadIdx.x;
    if (i < Eraw) atomicAdd(&d_deg[__ldg(&ei[Eraw + i])], 1);
}
__global__ void k_scan() {
    __shared__ int sP[1024];
    int tid = threadIdx.x;
    int base = tid * 16;
    int local[16];
    int run = 0;
    #pragma unroll
    for (int i = 0; i < 16; i++) { local[i] = run; run += d_deg[base + i]; }
    sP[tid] = run;
    __syncthreads();
    for (int off = 1; off < 1024; off <<= 1) {
        int v = (tid >= off) ? sP[tid - off] : 0;
        __syncthreads();
        sP[tid] += v;
        __syncthreads();
    }
    int pre = (tid == 0) ? 0 : sP[tid - 1];
    #pragma unroll
    for (int i = 0; i < 16; i++) {
        int n = base + i;
        int rs = pre + local[i];
        d_rowstart[n] = rs;
        d_cursor[n] = rs + 1;
        d_csrc[rs] = n;
    }
    if (tid == 1023) d_rowstart[NN] = sP[1023];
}
__global__ void k_scatter(const int* __restrict__ ei, int Eraw) {
    int i = blockIdx.x * blockDim.x + threadIdx.x;
    if (i >= Eraw) return;
    int s = __ldg(&ei[i]), d = __ldg(&ei[Eraw + i]);
    int pos = atomicAdd(&d_cursor[d], 1);
    d_csrc[pos] = s;
}

// ---------------- fused GAT layer 1 (H=2, C=64) ----------------
__global__ void k_gat1(const float* __restrict__ att, const float* __restrict__ bias1) {
    int w = (blockIdx.x * blockDim.x + threadIdx.x) >> 5;
    if (w >= NN) return;
    int lane = threadIdx.x & 31;
    float aA = att[lane], aB = att[lane + 32], aC = att[lane + 64], aD = att[lane + 96];
    const float* xr = d_xr1 + (size_t)w * 128;
    float r0 = xr[lane], r1 = xr[lane + 32], r2 = xr[lane + 64], r3 = xr[lane + 96];
    float acc0 = 0.f, acc1 = 0.f, acc2 = 0.f, acc3 = 0.f, s0 = 0.f, s1 = 0.f;
    int beg = d_rowstart[w], end = d_rowstart[w + 1];
    for (int i = beg; i < end; i++) {
        int s = d_csrc[i];
        const float* xl = d_xl1 + (size_t)s * 128;
        float v0 = xl[lane], v1 = xl[lane + 32], v2 = xl[lane + 64], v3 = xl[lane + 96];
        float t0 = v0 + r0; t0 = t0 > 0.f ? t0 : 0.2f * t0;
        float t1 = v1 + r1; t1 = t1 > 0.f ? t1 : 0.2f * t1;
        float t2 = v2 + r2; t2 = t2 > 0.f ? t2 : 0.2f * t2;
        float t3 = v3 + r3; t3 = t3 > 0.f ? t3 : 0.2f * t3;
        float p0 = t0 * aA + t1 * aB;
        float p1 = t2 * aC + t3 * aD;
        #pragma unroll
        for (int o = 16; o > 0; o >>= 1) {
            p0 += __shfl_xor_sync(0xFFFFFFFFu, p0, o);
            p1 += __shfl_xor_sync(0xFFFFFFFFu, p1, o);
        }
        float e0 = __expf(p0), e1 = __expf(p1);
        s0 += e0; s1 += e1;
        acc0 += e0 * v0; acc1 += e0 * v1; acc2 += e1 * v2; acc3 += e1 * v3;
    }
    float* o = d_h1 + (size_t)w * 128;
    float i0 = 1.f / s0, i1 = 1.f / s1;
    o[lane]      = bias1[lane]      + acc0 * i0;
    o[lane + 32] = bias1[lane + 32] + acc1 * i0;
    o[lane + 64] = bias1[lane + 64] + acc2 * i1;
    o[lane + 96] = bias1[lane + 96] + acc3 * i1;
}

// ---------------- fused GAT layer 2 (H=1, C=64) ----------------
__global__ void k_gat2(const float* __restrict__ att, const float* __restrict__ bias2) {
    int w = (blockIdx.x * blockDim.x + threadIdx.x) >> 5;
    if (w >= NN) return;
    int lane = threadIdx.x & 31;
    float aA = att[lane], aB = att[lane + 32];
    const float* xr = d_xr2 + (size_t)w * 64;
    float r0 = xr[lane], r1 = xr[lane + 32];
    float acc0 = 0.f, acc1 = 0.f, s0 = 0.f;
    int beg = d_rowstart[w], end = d_rowstart[w + 1];
    for (int i = beg; i < end; i++) {
        int s = d_csrc[i];
        const float* xl = d_xl2 + (size_t)s * 64;
        float v0 = xl[lane], v1 = xl[lane + 32];
        float t0 = v0 + r0; t0 = t0 > 0.f ? t0 : 0.2f * t0;
        float t1 = v1 + r1; t1 = t1 > 0.f ? t1 : 0.2f * t1;
        float p = t0 * aA + t1 * aB;
        #pragma unroll
        for (int o = 16; o > 0; o >>= 1) p += __shfl_xor_sync(0xFFFFFFFFu, p, o);
        float e = __expf(p);
        s0 += e;
        acc0 += e * v0; acc1 += e * v1;
    }
    float* o = d_h2 + (size_t)w * 64;
    float inv = 1.f / s0;
    o[lane]      = bias2[lane]      + acc0 * inv;
    o[lane + 32] = bias2[lane + 32] + acc1 * inv;
}

// ---------------- classifier ----------------
__global__ void k_cls(const float* __restrict__ Wc, const float* __restrict__ bc,
                      float* __restrict__ out) {
    int i = blockIdx.x * blockDim.x + threadIdx.x;
    if (i >= NN * 10) return;
    int n = i / 10, j = i % 10;
    const float* h = d_h2 + (size_t)n * 64;
    float acc = bc[j];
    #pragma unroll 16
    for (int k = 0; k < 64; k++) acc += h[k] * Wc[k * 10 + j];
    out[i] = acc;
}

// ---------------- launch ----------------
extern "C" void kernel_launch(void* const* d_in, const int* in_sizes, int n_in,
                              void* d_out, int out_size) {
    const float* x    = (const float*)d_in[0];
    const int*   ei   = (const int*)d_in[1];
    const float* c1w  = (const float*)d_in[2];
    const float* c1b  = (const float*)d_in[3];
    const float* c2w  = (const float*)d_in[4];
    const float* c2b  = (const float*)d_in[5];
    const float* Wl1  = (const float*)d_in[6];
    const float* bl1  = (const float*)d_in[7];
    const float* Wr1  = (const float*)d_in[8];
    const float* br1  = (const float*)d_in[9];
    const float* att1 = (const float*)d_in[10];
    const float* bias1= (const float*)d_in[11];
    const float* Wl2  = (const float*)d_in[12];
    const float* bl2  = (const float*)d_in[13];
    const float* Wr2  = (const float*)d_in[14];
    const float* br2  = (const float*)d_in[15];
    const float* att2 = (const float*)d_in[16];
    const float* bias2= (const float*)d_in[17];
    const float* Wc   = (const float*)d_in[18];
    const float* bc   = (const float*)d_in[19];
    float* out = (float*)d_out;

    int Eraw = in_sizes[1] / 2;
    int nodeBlocks = NN / 8;

    // Order keeps k_convf in ncu capture slot #4:
    // deg(1), hist(2), scan(3), convf(4), scatter(5), ...
    k_deg_init<<<NN / 256, 256>>>();
    k_hist<<<(Eraw + 255) / 256, 256>>>(ei, Eraw);
    k_scan<<<1, 1024>>>();
    k_convf<<<NN, 256>>>(x, c1w, c1b, c2w, c2b);
    k_scatter<<<(Eraw + 255) / 256, 256>>>(ei, Eraw);

    // GAT layer 1 (dual GEMM: xl1+xr1 in one pass over A)
    k_gemmd<0><<<dim3(2, NN / 128), 256>>>(Wl1, bl1, Wr1, br1, GIN, 128);
    k_gat1<<<nodeBlocks, 256>>>(att1, bias1);

    // GAT layer 2
    k_gemmd<1><<<dim3(1, NN / 128), 256>>>(Wl2, bl2, Wr2, br2, 128, 64);
    k_gat2<<<nodeBlocks, 256>>>(att2, bias2);

    // classifier
    k_cls<<<(NN * 10 + 255) / 256, 256>>>(Wc, bc, out);
}

// round 13
// speedup vs baseline: 1.0226x; 1.0226x over previous
#include <cuda_runtime.h>
#include <math.h>

#define NN 16384
#define GIN 1568
#define EMAX 540672   // 524288 + NN

// ---------------- scratch (static __device__, no allocation) ----------------
__device__ float d_h0[(size_t)NN * GIN];
__device__ float d_xl1[(size_t)NN * 128];
__device__ float d_xr1[(size_t)NN * 128];
__device__ float d_h1[(size_t)NN * 128];
__device__ float d_xl2[(size_t)NN * 64];
__device__ float d_xr2[(size_t)NN * 64];
__device__ float d_h2[(size_t)NN * 64];
__device__ int d_deg[NN];          // zero-init; k_scan re-zeroes after use
__device__ int d_rowstart[NN + 1];
__device__ int d_cursor[NN];
__device__ int d_csrc[EMAX];

// ---------------- helpers ----------------
__device__ __forceinline__ unsigned f2tf32(float x) {
    unsigned u;
    asm("cvt.rna.tf32.f32 %0, %1;" : "=r"(u) : "f"(x));
    return u;
}
__device__ __forceinline__ void mma_tf32(float* d, const unsigned* a, const unsigned* b) {
    asm volatile(
        "mma.sync.aligned.m16n8k8.row.col.f32.tf32.tf32.f32 "
        "{%0,%1,%2,%3}, {%4,%5,%6,%7}, {%8,%9}, {%0,%1,%2,%3};\n"
        : "+f"(d[0]), "+f"(d[1]), "+f"(d[2]), "+f"(d[3])
        : "r"(a[0]), "r"(a[1]), "r"(a[2]), "r"(a[3]), "r"(b[0]), "r"(b[1]));
}
__device__ __forceinline__ unsigned smaddr(const void* p) {
    unsigned a;
    asm("{ .reg .u64 t; cvta.to.shared.u64 t, %1; cvt.u32.u64 %0, t; }" : "=r"(a) : "l"(p));
    return a;
}
__device__ __forceinline__ void cp16(unsigned d, const void* s) {
    asm volatile("cp.async.cg.shared.global [%0], [%1], 16;" :: "r"(d), "l"(s));
}

// ---------------- fused conv1+pool+conv2+pool (tf32 implicit GEMM) ----------------
// Smem (words, 10948 = 43.8KB; reg-capped at 4 blocks/SM anyway):
//   [0..4100)       sInP: 16ci x 256 padded conv1 out, tf32 bits
//   [4100..4884)    sImg (conv1 phase)
//   [4884..5028)    sW1 ; [5028..5044) sB1
//   [5044..10804)   Bs[144][40]  (BP=40: B-frag LDS conflict-free, 8t+g mod 32)
//   [10804..10948)  offT[144]
//   epilogue: sC[224][33] overlays [0..7392)
#define C2_BP 40
__global__ void k_convf(const float* __restrict__ x,
                        const float* __restrict__ w1,
                        const float* __restrict__ b1,
                        const float* __restrict__ w2,
                        const float* __restrict__ b2) {
    __shared__ float S[10948];
    unsigned* sInP = (unsigned*)S;
    float*    sImg = S + 4100;
    float*    sW1  = S + 4884;
    float*    sB1  = S + 5028;
    unsigned* Bs   = (unsigned*)(S + 5044);
    int*      offT = (int*)(S + 10804);
    float*    sC   = S;

    int n = blockIdx.x, tid = threadIdx.x;

    for (int i = tid; i < 4100; i += 256) sInP[i] = 0u;
    const float* xp = x + (size_t)n * 784;
    for (int i = tid; i < 784; i += 256) sImg[i] = xp[i];
    if (tid < 144) sW1[tid] = w1[tid];
    if (tid < 16) sB1[tid] = b1[tid];
    if (tid < 144) {
        int ci = tid / 9, rem = tid - ci * 9;
        offT[tid] = ci * 256 + (rem / 3) * 16 + (rem % 3);
    }
    __syncthreads();

    // ---- conv1 phase: threads <196 = one pooled pos each, patch loaded ONCE,
    //      all 16 channels; threads >=196 stage conv2 weights concurrently ----
    if (tid < 196) {
        int py = tid / 14, px = tid - py * 14;
        int y0 = 2 * py - 1, x0 = 2 * px - 1;
        float patch[4][4];
        #pragma unroll
        for (int r = 0; r < 4; r++) {
            int iy = y0 + r;
            bool okY = (unsigned)iy < 28u;
            #pragma unroll
            for (int cc = 0; cc < 4; cc++) {
                int ix = x0 + cc;
                patch[r][cc] = (okY && (unsigned)ix < 28u) ? sImg[iy * 28 + ix] : 0.f;
            }
        }
        int obase = (py + 1) * 16 + px + 1;
        #pragma unroll
        for (int c = 0; c < 16; c++) {
            float bb = sB1[c];
            float a0 = bb, a1 = bb, a2 = bb, a3 = bb;
            const float* wp = &sW1[c * 9];
            #pragma unroll
            for (int ky = 0; ky < 3; ky++) {
                #pragma unroll
                for (int kx = 0; kx < 3; kx++) {
                    float wv = wp[ky * 3 + kx];
                    a0 += patch[ky][kx]         * wv;
                    a1 += patch[ky][kx + 1]     * wv;
                    a2 += patch[ky + 1][kx]     * wv;
                    a3 += patch[ky + 1][kx + 1] * wv;
                }
            }
            float best = fmaxf(fmaxf(a0, a1), fmaxf(a2, a3));
            sInP[c * 256 + obase] = f2tf32(fmaxf(best, 0.f));
        }
    } else {
        // 60 threads stage Bs: w2 (32,16,3,3) -> Bs[k][oc]
        for (int i = tid - 196; i < 4608; i += 60) {
            int oc = i / 144, k = i - oc * 144;
            Bs[k * C2_BP + oc] = f2tf32(__ldg(&w2[i]));
        }
    }
    __syncthreads();

    // ---- conv2 mainloop ----
    int warp = tid >> 5, lane = tid & 31;
    int g = lane >> 2, t = lane & 3;

    float acc[2][4][4] = {};

    #pragma unroll
    for (int chunk = 0; chunk < 9; chunk++) {
        int c16 = chunk * 16;
        int o0 = offT[c16 + t];
        int o1 = offT[c16 + t + 4];
        int o2 = offT[c16 + t + 8];
        int o3 = offT[c16 + t + 12];
        #pragma unroll
        for (int kb = 0; kb < 2; kb++) {
            int oA = kb ? o2 : o0, oB = kb ? o3 : o1;
            int krow = c16 + kb * 8;
            unsigned bfr[4][2];
            #pragma unroll
            for (int ni = 0; ni < 4; ni++) {
                bfr[ni][0] = Bs[(krow + t) * C2_BP + ni * 8 + g];
                bfr[ni][1] = Bs[(krow + t + 4) * C2_BP + ni * 8 + g];
            }
            #pragma unroll
            for (int mi = 0; mi < 2; mi++) {
                int mt = warp + mi * 8;
                if (mt < 14) {
                    int m = mt * 16;
                    unsigned a[4];
                    a[0] = sInP[oA + m + g];
                    a[1] = sInP[oA + m + g + 8];
                    a[2] = sInP[oB + m + g];
                    a[3] = sInP[oB + m + g + 8];
                    #pragma unroll
                    for (int ni = 0; ni < 4; ni++)
                        mma_tf32(acc[mi][ni], a, bfr[ni]);
                }
            }
        }
    }
    __syncthreads();

    #pragma unroll
    for (int mi = 0; mi < 2; mi++) {
        int mt = warp + mi * 8;
        if (mt < 14) {
            int row0 = mt * 16 + g;
            #pragma unroll
            for (int ni = 0; ni < 4; ni++) {
                int col = ni * 8 + t * 2;
                sC[row0 * 33 + col]           = acc[mi][ni][0];
                sC[row0 * 33 + col + 1]       = acc[mi][ni][1];
                sC[(row0 + 8) * 33 + col]     = acc[mi][ni][2];
                sC[(row0 + 8) * 33 + col + 1] = acc[mi][ni][3];
            }
        }
    }
    __syncthreads();

    for (int o = tid; o < 1568; o += 256) {
        int oc = o / 49, p = o - oc * 49;
        int py = p / 7, px = p - py * 7;
        int pos00 = py * 32 + px * 2;
        float v = fmaxf(fmaxf(sC[pos00 * 33 + oc],        sC[(pos00 + 1) * 33 + oc]),
                        fmaxf(sC[(pos00 + 16) * 33 + oc], sC[(pos00 + 17) * 33 + oc]));
        v += __ldg(&b2[oc]);
        d_h0[(size_t)n * 1568 + o] = fmaxf(v, 0.f);
    }
}

// ---------------- dual tf32 GEMM: stages A once, computes l AND r outputs ----------------
template <int SEL>
__global__ void k_gemmd(const float* __restrict__ Bl, const float* __restrict__ biasl,
                        const float* __restrict__ Br, const float* __restrict__ biasr,
                        int K, int Nc) {
    const float* A = (SEL == 0) ? d_h0 : d_h1;
    float* Cl = (SEL == 0) ? d_xl1 : d_xl2;
    float* Cr = (SEL == 0) ? d_xr1 : d_xr2;

    __shared__ float As[2][128][20];
    __shared__ float Bsl[2][16][72];
    __shared__ float Bsr[2][16][72];

    int bm = blockIdx.y * 128, bn = blockIdx.x * 64;
    int tid = threadIdx.x;
    int warp = tid >> 5, lane = tid & 31;
    int g = lane >> 2, t = lane & 3;
    int mW = (warp >> 1) * 32, nW = (warp & 1) * 32;

    int arow = tid >> 1, akq = (tid & 1) * 8;
    int brow = tid >> 4, bq = (tid & 15) * 4;

    const float* aSrc  = A + (size_t)(bm + arow) * K + akq;
    const float* blSrc = Bl + (size_t)brow * Nc + bn + bq;
    const float* brSrc = Br + (size_t)brow * Nc + bn + bq;

    float accL[2][4][4] = {}, accR[2][4][4] = {};
    int niter = K >> 4;

    cp16(smaddr(&As[0][arow][akq]),     aSrc);
    cp16(smaddr(&As[0][arow][akq + 4]), aSrc + 4);
    cp16(smaddr(&Bsl[0][brow][bq]),     blSrc);
    cp16(smaddr(&Bsr[0][brow][bq]),     brSrc);
    asm volatile("cp.async.commit_group;");

    for (int it = 0; it < niter; it++) {
        int buf = it & 1;
        if (it + 1 < niter) {
            int k0 = (it + 1) << 4;
            cp16(smaddr(&As[buf ^ 1][arow][akq]),     aSrc + k0);
            cp16(smaddr(&As[buf ^ 1][arow][akq + 4]), aSrc + k0 + 4);
            cp16(smaddr(&Bsl[buf ^ 1][brow][bq]),     blSrc + (size_t)k0 * Nc);
            cp16(smaddr(&Bsr[buf ^ 1][brow][bq]),     brSrc + (size_t)k0 * Nc);
            asm volatile("cp.async.commit_group;");
            asm volatile("cp.async.wait_group 1;");
        } else {
            asm volatile("cp.async.wait_group 0;");
        }
        __syncthreads();

        #pragma unroll
        for (int kb = 0; kb < 2; kb++) {
            int kk = kb * 8;
            unsigned a[2][4], bL[4][2], bR[4][2];
            #pragma unroll
            for (int mi = 0; mi < 2; mi++) {
                int mrow = mW + mi * 16;
                float x0 = As[buf][mrow + g][kk + t];
                float x1 = As[buf][mrow + g + 8][kk + t];
                float x2 = As[buf][mrow + g][kk + t + 4];
                float x3 = As[buf][mrow + g + 8][kk + t + 4];
                if (SEL == 1) {
                    x0 = fmaxf(x0, 0.f); x1 = fmaxf(x1, 0.f);
                    x2 = fmaxf(x2, 0.f); x3 = fmaxf(x3, 0.f);
                }
                a[mi][0] = f2tf32(x0); a[mi][1] = f2tf32(x1);
                a[mi][2] = f2tf32(x2); a[mi][3] = f2tf32(x3);
            }
            #pragma unroll
            for (int ni = 0; ni < 4; ni++) {
                bL[ni][0] = f2tf32(Bsl[buf][kk + t][nW + ni * 8 + g]);
                bL[ni][1] = f2tf32(Bsl[buf][kk + t + 4][nW + ni * 8 + g]);
                bR[ni][0] = f2tf32(Bsr[buf][kk + t][nW + ni * 8 + g]);
                bR[ni][1] = f2tf32(Bsr[buf][kk + t + 4][nW + ni * 8 + g]);
            }
            #pragma unroll
            for (int mi = 0; mi < 2; mi++)
                #pragma unroll
                for (int ni = 0; ni < 4; ni++) {
                    mma_tf32(accL[mi][ni], a[mi], bL[ni]);
                    mma_tf32(accR[mi][ni], a[mi], bR[ni]);
                }
        }
        __syncthreads();
    }

    #pragma unroll
    for (int mi = 0; mi < 2; mi++) {
        int row0 = bm + mW + mi * 16 + g;
        #pragma unroll
        for (int ni = 0; ni < 4; ni++) {
            int col = bn + nW + ni * 8 + t * 2;
            float bl0 = biasl[col], bl1 = biasl[col + 1];
            float br0 = biasr[col], br1 = biasr[col + 1];
            Cl[(size_t)row0 * Nc + col]           = accL[mi][ni][0] + bl0;
            Cl[(size_t)row0 * Nc + col + 1]       = accL[mi][ni][1] + bl1;
            Cl[(size_t)(row0 + 8) * Nc + col]     = accL[mi][ni][2] + bl0;
            Cl[(size_t)(row0 + 8) * Nc + col + 1] = accL[mi][ni][3] + bl1;
            Cr[(size_t)row0 * Nc + col]           = accR[mi][ni][0] + br0;
            Cr[(size_t)row0 * Nc + col + 1]       = accR[mi][ni][1] + br1;
            Cr[(size_t)(row0 + 8) * Nc + col]     = accR[mi][ni][2] + br0;
            Cr[(size_t)(row0 + 8) * Nc + col + 1] = accR[mi][ni][3] + br1;
        }
    }
}

// ---------------- CSR build (deg_init folded into scan) ----------------
__global__ void k_hist(const int* __restrict__ ei, int Eraw) {
    int i = blockIdx.x * blockDim.x + threadIdx.x;
    if (i < Eraw) atomicAdd(&d_deg[__ldg(&ei[Eraw + i])], 1);
}
__global__ void k_scan() {
    __shared__ int sP[1024];
    int tid = threadIdx.x;
    int base = tid * 16;
    int local[16];
    int run = 0;
    #pragma unroll
    for (int i = 0; i < 16; i++) {
        local[i] = run;
        run += d_deg[base + i] + 1;   // +1 = self loop
        d_deg[base + i] = 0;          // re-zero for next graph replay
    }
    sP[tid] = run;
    __syncthreads();
    for (int off = 1; off < 1024; off <<= 1) {
        int v = (tid >= off) ? sP[tid - off] : 0;
        __syncthreads();
        sP[tid] += v;
        __syncthreads();
    }
    int pre = (tid == 0) ? 0 : sP[tid - 1];
    #pragma unroll
    for (int i = 0; i < 16; i++) {
        int n = base + i;
        int rs = pre + local[i];
        d_rowstart[n] = rs;
        d_cursor[n] = rs + 1;   // slot 0 = self loop
        d_csrc[rs] = n;
    }
    if (tid == 1023) d_rowstart[NN] = sP[1023];
}
__global__ void k_scatter(const int* __restrict__ ei, int Eraw) {
    int i = blockIdx.x * blockDim.x + threadIdx.x;
    if (i >= Eraw) return;
    int s = __ldg(&ei[i]), d = __ldg(&ei[Eraw + i]);
    int pos = atomicAdd(&d_cursor[d], 1);
    d_csrc[pos] = s;
}

// ---------------- fused GAT layer 1 (H=2, C=64), edge-ahead pipelined ----------------
__global__ void k_gat1(const float* __restrict__ att, const float* __restrict__ bias1) {
    int w = (blockIdx.x * blockDim.x + threadIdx.x) >> 5;
    if (w >= NN) return;
    int lane = threadIdx.x & 31;
    float aA = att[lane], aB = att[lane + 32], aC = att[lane + 64], aD = att[lane + 96];
    const float* xr = d_xr1 + (size_t)w * 128;
    float r0 = xr[lane], r1 = xr[lane + 32], r2 = xr[lane + 64], r3 = xr[lane + 96];
    float acc0 = 0.f, acc1 = 0.f, acc2 = 0.f, acc3 = 0.f, s0 = 0.f, s1 = 0.f;
    int beg = d_rowstart[w], end = d_rowstart[w + 1];

    // prologue: load edge beg
    const float* xl = d_xl1 + (size_t)d_csrc[beg] * 128;
    float w0 = xl[lane], w1 = xl[lane + 32], w2 = xl[lane + 64], w3 = xl[lane + 96];

    for (int i = beg; i < end; i++) {
        float v0 = w0, v1 = w1, v2 = w2, v3 = w3;
        if (i + 1 < end) {   // issue next edge's loads before compute
            const float* xn = d_xl1 + (size_t)d_csrc[i + 1] * 128;
            w0 = xn[lane]; w1 = xn[lane + 32]; w2 = xn[lane + 64]; w3 = xn[lane + 96];
        }
        float t0 = v0 + r0; t0 = t0 > 0.f ? t0 : 0.2f * t0;
        float t1 = v1 + r1; t1 = t1 > 0.f ? t1 : 0.2f * t1;
        float t2 = v2 + r2; t2 = t2 > 0.f ? t2 : 0.2f * t2;
        float t3 = v3 + r3; t3 = t3 > 0.f ? t3 : 0.2f * t3;
        float p0 = t0 * aA + t1 * aB;
        float p1 = t2 * aC + t3 * aD;
        #pragma unroll
        for (int o = 16; o > 0; o >>= 1) {
            p0 += __shfl_xor_sync(0xFFFFFFFFu, p0, o);
            p1 += __shfl_xor_sync(0xFFFFFFFFu, p1, o);
        }
        float e0 = __expf(p0), e1 = __expf(p1);
        s0 += e0; s1 += e1;
        acc0 += e0 * v0; acc1 += e0 * v1; acc2 += e1 * v2; acc3 += e1 * v3;
    }
    float* o = d_h1 + (size_t)w * 128;
    float i0 = 1.f / s0, i1 = 1.f / s1;
    o[lane]      = bias1[lane]      + acc0 * i0;
    o[lane + 32] = bias1[lane + 32] + acc1 * i0;
    o[lane + 64] = bias1[lane + 64] + acc2 * i1;
    o[lane + 96] = bias1[lane + 96] + acc3 * i1;
}

// ---------------- fused GAT layer 2 (H=1, C=64), edge-ahead pipelined ----------------
__global__ void k_gat2(const float* __restrict__ att, const float* __restrict__ bias2) {
    int w = (blockIdx.x * blockDim.x + threadIdx.x) >> 5;
    if (w >= NN) return;
    int lane = threadIdx.x & 31;
    float aA = att[lane], aB = att[lane + 32];
    const float* xr = d_xr2 + (size_t)w * 64;
    float r0 = xr[lane], r1 = xr[lane + 32];
    float acc0 = 0.f, acc1 = 0.f, s0 = 0.f;
    int beg = d_rowstart[w], end = d_rowstart[w + 1];

    const float* xl = d_xl2 + (size_t)d_csrc[beg] * 64;
    float w0 = xl[lane], w1 = xl[lane + 32];

    for (int i = beg; i < end; i++) {
        float v0 = w0, v1 = w1;
        if (i + 1 < end) {
            const float* xn = d_xl2 + (size_t)d_csrc[i + 1] * 64;
            w0 = xn[lane]; w1 = xn[lane + 32];
        }
        float t0 = v0 + r0; t0 = t0 > 0.f ? t0 : 0.2f * t0;
        float t1 = v1 + r1; t1 = t1 > 0.f ? t1 : 0.2f * t1;
        float p = t0 * aA + t1 * aB;
        #pragma unroll
        for (int o = 16; o > 0; o >>= 1) p += __shfl_xor_sync(0xFFFFFFFFu, p, o);
        float e = __expf(p);
        s0 += e;
        acc0 += e * v0; acc1 += e * v1;
    }
    float* o = d_h2 + (size_t)w * 64;
    float inv = 1.f / s0;
    o[lane]      = bias2[lane]      + acc0 * inv;
    o[lane + 32] = bias2[lane + 32] + acc1 * inv;
}

// ---------------- classifier ----------------
__global__ void k_cls(const float* __restrict__ Wc, const float* __restrict__ bc,
                      float* __restrict__ out) {
    int i = blockIdx.x * blockDim.x + threadIdx.x;
    if (i >= NN * 10) return;
    int n = i / 10, j = i % 10;
    const float* h = d_h2 + (size_t)n * 64;
    float acc = bc[j];
    #pragma unroll 16
    for (int k = 0; k < 64; k++) acc += h[k] * Wc[k * 10 + j];
    out[i] = acc;
}

// ---------------- launch ----------------
extern "C" void kernel_launch(void* const* d_in, const int* in_sizes, int n_in,
                              void* d_out, int out_size) {
    const float* x    = (const float*)d_in[0];
    const int*   ei   = (const int*)d_in[1];
    const float* c1w  = (const float*)d_in[2];
    const float* c1b  = (const float*)d_in[3];
    const float* c2w  = (const float*)d_in[4];
    const float* c2b  = (const float*)d_in[5];
    const float* Wl1  = (const float*)d_in[6];
    const float* bl1  = (const float*)d_in[7];
    const float* Wr1  = (const float*)d_in[8];
    const float* br1  = (const float*)d_in[9];
    const float* att1 = (const float*)d_in[10];
    const float* bias1= (const float*)d_in[11];
    const float* Wl2  = (const float*)d_in[12];
    const float* bl2  = (const float*)d_in[13];
    const float* Wr2  = (const float*)d_in[14];
    const float* br2  = (const float*)d_in[15];
    const float* att2 = (const float*)d_in[16];
    const float* bias2= (const float*)d_in[17];
    const float* Wc   = (const float*)d_in[18];
    const float* bc   = (const float*)d_in[19];
    float* out = (float*)d_out;

    int Eraw = in_sizes[1] / 2;
    int nodeBlocks = NN / 8;

    // Slot order: hist(1), scan(2), scatter(3), convf(4 = ncu capture slot), ...
    k_hist<<<(Eraw + 255) / 256, 256>>>(ei, Eraw);
    k_scan<<<1, 1024>>>();
    k_scatter<<<(Eraw + 255) / 256, 256>>>(ei, Eraw);
    k_convf<<<NN, 256>>>(x, c1w, c1b, c2w, c2b);

    // GAT layer 1 (dual GEMM: xl1+xr1 in one pass over A)
    k_gemmd<0><<<dim3(2, NN / 128), 256>>>(Wl1, bl1, Wr1, br1, GIN, 128);
    k_gat1<<<nodeBlocks, 256>>>(att1, bias1);

    // GAT layer 2
    k_gemmd<1><<<dim3(1, NN / 128), 256>>>(Wl2, bl2, Wr2, br2, 128, 64);
    k_gat2<<<nodeBlocks, 256>>>(att2, bias2);

    // classifier
    k_cls<<<(NN * 10 + 255) / 256, 256>>>(Wc, bc, out);
}